// round 8
// baseline (speedup 1.0000x reference)
#include <cuda_runtime.h>
#include <cuda_bf16.h>
#include <math.h>
#include <stdint.h>

#define B_SZ 64
#define T_SZ 128
#define F_SZ 512
#define H_SZ 1024
#define P_SZ 1024
#define A_SZ 32
#define R_SZ 8192
#define G_SZ 4096
#define S_ST 3          /* cp.async stages for big GEMM */

#define PK_CTAS 128
#define PK_TILES 32
#define PK_KS 4
#define PK_KCH 12       /* 12 chunks of 64 over K-split of 768 */
#define PK_AST 3        /* A pipeline stages */
#define B_CHB 16384
#define A_CHB 8192
#define Z_BUF 8192

typedef __nv_bfloat16 bf16;

// ---------------- scratch (static device globals) ---------------------------
__device__ float g_pre[(size_t)R_SZ * P_SZ];
__device__ float g_zx[(size_t)R_SZ * G_SZ];              // time-major [T][B][4H-permuted]
__device__ float g_zpart[PK_KS][(size_t)B_SZ * G_SZ];    // split-K partials (permuted cols)
__device__ float g_c[B_SZ * H_SZ];
__device__ float g_h[B_SZ * H_SZ];
__device__ unsigned g_full_cnt;
__device__ unsigned g_mini_cnt[PK_TILES];

__device__ __align__(256) bf16 g_Ax  [(size_t)R_SZ * 3 * F_SZ];
__device__ __align__(256) bf16 g_Aln [(size_t)R_SZ * 3 * P_SZ];
__device__ __align__(256) bf16 g_Aseq0[(size_t)R_SZ * 3 * H_SZ];
__device__ __align__(256) bf16 g_Aseq1[(size_t)R_SZ * 3 * H_SZ];
__device__ __align__(256) bf16 g_Ahp [(size_t)R_SZ * 3 * P_SZ];
__device__ __align__(256) bf16 g_Ah  [B_SZ * 3 * H_SZ];

__device__ __align__(256) bf16 g_Bpre [(size_t)P_SZ * 3 * F_SZ];
__device__ __align__(256) bf16 g_Bwi0 [(size_t)G_SZ * 3 * P_SZ];
__device__ __align__(256) bf16 g_Bwh0 [(size_t)G_SZ * 3 * H_SZ];   // N-permuted
__device__ __align__(256) bf16 g_Bwi1 [(size_t)G_SZ * 3 * H_SZ];
__device__ __align__(256) bf16 g_Bwh1 [(size_t)G_SZ * 3 * H_SZ];   // N-permuted
__device__ __align__(256) bf16 g_Bpost[(size_t)P_SZ * 3 * H_SZ];
__device__ __align__(256) bf16 g_Bout [(size_t)A_SZ * 3 * P_SZ];

// ---------------- helpers ---------------------------------------------------
__device__ __forceinline__ uint32_t smem_u32(const void* p) {
    uint32_t a;
    asm("{ .reg .u64 t; cvta.to.shared.u64 t, %1; cvt.u32.u64 %0, t; }" : "=r"(a) : "l"(p));
    return a;
}
#define SMEM_SWZ(o) ((o) ^ (((o) >> 3) & 0x70))
#define CP_ASYNC16(dst, src) \
    asm volatile("cp.async.cg.shared.global [%0], [%1], 16;" :: "r"(dst), "l"(src))
#define CP_COMMIT() asm volatile("cp.async.commit_group;" ::: "memory")
#define CP_WAIT0()  asm volatile("cp.async.wait_group 0;" ::: "memory")
#define CP_WAIT2()  asm volatile("cp.async.wait_group 2;" ::: "memory")

__device__ __forceinline__ void ldmx4(uint32_t* r, uint32_t addr) {
    asm volatile("ldmatrix.sync.aligned.m8n8.x4.shared.b16 {%0,%1,%2,%3}, [%4];"
                 : "=r"(r[0]), "=r"(r[1]), "=r"(r[2]), "=r"(r[3]) : "r"(addr));
}
__device__ __forceinline__ void mma16816(float* c, const uint32_t* a, const uint32_t* b) {
    asm volatile("mma.sync.aligned.m16n8k16.row.col.f32.bf16.bf16.f32 "
                 "{%0,%1,%2,%3}, {%4,%5,%6,%7}, {%8,%9}, {%0,%1,%2,%3};"
                 : "+f"(c[0]), "+f"(c[1]), "+f"(c[2]), "+f"(c[3])
                 : "r"(a[0]), "r"(a[1]), "r"(a[2]), "r"(a[3]), "r"(b[0]), "r"(b[1]));
}
__device__ __forceinline__ void split2(float v, bf16& hi, bf16& lo) {
    hi = __float2bfloat16_rn(v);
    lo = __float2bfloat16_rn(v - __bfloat162float(hi));
}
__device__ __forceinline__ float sigmoidf_(float x) { return 1.f / (1.f + expf(-x)); }

// ---------------- big HMMA GEMM (feed-forward ops) ---------------------------
// OUTMODE 0: fp32 row-major (+bias). 1: fp32 time-major [T][B][N] PERMUTED cols.
//         2: bf16-split [M, 3*Ntot] (+bias, relu).
template <int BM, int BN, int OUTMODE>
__global__ __launch_bounds__(256, 1) void gemm_mma(
    const bf16* __restrict__ Ap, const bf16* __restrict__ Bp,
    const float* __restrict__ bias, float* __restrict__ Cf,
    bf16* __restrict__ Cb, int Ntot, int K3)
{
    constexpr int WM = (BN == 32) ? 4 : 2;
    constexpr int WN = 8 / WM;
    constexpr int TM = BM / WM;
    constexpr int TN = BN / WN;
    constexpr int MT = TM / 16;
    constexpr int NT = TN / 8;
    constexpr int ABYTES = BM * 128;
    constexpr int BBYTES = BN * 128;

    extern __shared__ __align__(1024) char smem[];
    const uint32_t sA = smem_u32(smem);
    const uint32_t sB = sA + S_ST * ABYTES;

    const int tid = threadIdx.x;
    const int lane = tid & 31, wid = tid >> 5;
    const int wm = wid % WM, wn = wid / WM;
    const int bm = blockIdx.y * BM;
    const int bn = blockIdx.x * BN;
    const int NC = K3 / 64;

    const char* Ag = (const char*)(Ap + (size_t)bm * K3);
    const char* Bg = (const char*)(Bp + (size_t)bn * K3);
    const size_t rowB = (size_t)K3 * 2;

    float acc[MT][NT][4];
#pragma unroll
    for (int i = 0; i < MT; i++)
#pragma unroll
        for (int j = 0; j < NT; j++)
#pragma unroll
            for (int q = 0; q < 4; q++) acc[i][j][q] = 0.f;

    auto load_chunk = [&](int c, int stage) {
        const size_t coff = (size_t)c * 128;
        const uint32_t aT = sA + stage * ABYTES;
        const uint32_t bT = sB + stage * BBYTES;
#pragma unroll
        for (int i = 0; i < BM / 32; i++) {
            int seg = tid + i * 256, row = seg >> 3, so = (seg & 7) * 16;
            CP_ASYNC16(aT + SMEM_SWZ(row * 128 + so), Ag + (size_t)row * rowB + coff + so);
        }
#pragma unroll
        for (int i = 0; i < BN / 32; i++) {
            int seg = tid + i * 256, row = seg >> 3, so = (seg & 7) * 16;
            CP_ASYNC16(bT + SMEM_SWZ(row * 128 + so), Bg + (size_t)row * rowB + coff + so);
        }
    };

    load_chunk(0, 0); CP_COMMIT();
    load_chunk(1, 1); CP_COMMIT();

    const int a_row = wm * TM + (lane & 15);
    const int a_k16 = (lane >> 4) * 16;
    const int b_row = wn * TN + (lane & 7) + ((lane >> 4) << 3);
    const int b_k16 = ((lane >> 3) & 1) * 16;

    for (int c = 0; c < NC; c++) {
        int n = c + 2;
        if (n < NC) load_chunk(n, n % S_ST);
        CP_COMMIT();
        CP_WAIT2();
        __syncthreads();

        const uint32_t aT = sA + (c % S_ST) * ABYTES;
        const uint32_t bT = sB + (c % S_ST) * BBYTES;
#pragma unroll
        for (int ks = 0; ks < 4; ks++) {
            uint32_t af[MT][4], bfr[NT][2];
#pragma unroll
            for (int i = 0; i < MT; i++)
                ldmx4(af[i], aT + SMEM_SWZ((a_row + i * 16) * 128 + ks * 32 + a_k16));
#pragma unroll
            for (int jp = 0; jp < NT / 2; jp++) {
                uint32_t t4[4];
                ldmx4(t4, bT + SMEM_SWZ((b_row + jp * 16) * 128 + ks * 32 + b_k16));
                bfr[2 * jp][0] = t4[0]; bfr[2 * jp][1] = t4[1];
                bfr[2 * jp + 1][0] = t4[2]; bfr[2 * jp + 1][1] = t4[3];
            }
#pragma unroll
            for (int i = 0; i < MT; i++)
#pragma unroll
                for (int j = 0; j < NT; j++)
                    mma16816(acc[i][j], af[i], bfr[j]);
        }
        __syncthreads();
    }

#pragma unroll
    for (int i = 0; i < MT; i++) {
        const int r0 = bm + wm * TM + i * 16 + (lane >> 2);
        const int r1 = r0 + 8;
#pragma unroll
        for (int j = 0; j < NT; j++) {
            const int col = bn + wn * TN + j * 8 + (lane & 3) * 2;
            const float2 bv = *(const float2*)&bias[col];
            float v00 = acc[i][j][0] + bv.x, v01 = acc[i][j][1] + bv.y;
            float v10 = acc[i][j][2] + bv.x, v11 = acc[i][j][3] + bv.y;
            if (OUTMODE == 0) {
                *(float2*)&Cf[(size_t)r0 * Ntot + col] = make_float2(v00, v01);
                *(float2*)&Cf[(size_t)r1 * Ntot + col] = make_float2(v10, v11);
            } else if (OUTMODE == 1) {
                int b0i = r0 >> 7, t0 = r0 & 127, b1i = r1 >> 7, t1 = r1 & 127;
                int c0p = (col & 1023) * 4 + (col >> 10);
                int c1p = ((col + 1) & 1023) * 4 + ((col + 1) >> 10);
                float* q0 = Cf + ((size_t)t0 * B_SZ + b0i) * Ntot;
                float* q1 = Cf + ((size_t)t1 * B_SZ + b1i) * Ntot;
                q0[c0p] = v00; q0[c1p] = v01;
                q1[c0p] = v10; q1[c1p] = v11;
            } else {
                v00 = fmaxf(v00, 0.f); v01 = fmaxf(v01, 0.f);
                v10 = fmaxf(v10, 0.f); v11 = fmaxf(v11, 0.f);
                bf16 h0, l0, h1, l1;
                bf16* row0 = Cb + (size_t)r0 * 3 * Ntot;
                bf16* row1 = Cb + (size_t)r1 * 3 * Ntot;
                split2(v00, h0, l0); split2(v01, h1, l1);
                *(__nv_bfloat162*)&row0[col] = __nv_bfloat162(h0, h1);
                *(__nv_bfloat162*)&row0[Ntot + col] = __nv_bfloat162(h0, h1);
                *(__nv_bfloat162*)&row0[2 * Ntot + col] = __nv_bfloat162(l0, l1);
                split2(v10, h0, l0); split2(v11, h1, l1);
                *(__nv_bfloat162*)&row1[col] = __nv_bfloat162(h0, h1);
                *(__nv_bfloat162*)&row1[Ntot + col] = __nv_bfloat162(h0, h1);
                *(__nv_bfloat162*)&row1[2 * Ntot + col] = __nv_bfloat162(l0, l1);
            }
        }
    }
}

// ---------------- persistent LSTM recurrence ---------------------------------
// 128 CTAs = 32 N-tiles (128 permuted cols) x 4 K-splits (768 of K3=3072).
// Wh' SMEM-resident; A streamed (3 stages); zx prefetched to SMEM per step;
// gates distributed over all CTAs (split by batch).
__global__ __launch_bounds__(256, 1) void lstm_persistent(
    const bf16* __restrict__ Bwh, const float* __restrict__ zx,
    bf16* __restrict__ Aseq)
{
    extern __shared__ __align__(1024) char smem[];
    const uint32_t sB = smem_u32(smem);
    const uint32_t sA = sB + PK_KCH * B_CHB;
    char* zbuf = smem + PK_KCH * B_CHB + PK_AST * A_CHB;
    const uint32_t sZ = smem_u32(zbuf);

    const int tid = threadIdx.x;
    const int lane = tid & 31, wid = tid >> 5;
    const int tile = blockIdx.x >> 2;
    const int ks = blockIdx.x & 3;
    const int wm = wid & 1, wn = wid >> 1;      // TM=32, TN=32
    const int bn = tile * 128;
    const int b0 = ks * 16;                     // gate batch base
    const size_t rowB = 3072 * 2;

    // load resident Wh' slice: 12 chunks x (128 rows x 128B), SW128
    const char* Bg = (const char*)Bwh + (size_t)bn * rowB + ks * 1536;
    for (int ch = 0; ch < PK_KCH; ch++)
#pragma unroll
        for (int i = 0; i < 4; i++) {
            int seg = tid + i * 256, row = seg >> 3, so = (seg & 7) * 16;
            CP_ASYNC16(sB + ch * B_CHB + SMEM_SWZ(row * 128 + so),
                       Bg + (size_t)row * rowB + ch * 128 + so);
        }
    CP_COMMIT();
    CP_WAIT0();
    __syncthreads();

    const char* Ag = (const char*)g_Ah + ks * 1536;
    float* zp = g_zpart[ks];

    const int a_row = wm * 32 + (lane & 15);
    const int a_k16 = (lane >> 4) * 16;
    const int b_row = wn * 32 + (lane & 7) + ((lane >> 4) << 3);
    const int b_k16 = ((lane >> 3) & 1) * 16;

    for (int t = 0; t < T_SZ; t++) {
        float acc[2][4][4];
#pragma unroll
        for (int i = 0; i < 2; i++)
#pragma unroll
            for (int j = 0; j < 4; j++)
#pragma unroll
                for (int q = 0; q < 4; q++) acc[i][j][q] = 0.f;

        auto loadA = [&](int ch, int st) {
#pragma unroll
            for (int i = 0; i < 2; i++) {
                int seg = tid + i * 256, row = seg >> 3, so = (seg & 7) * 16;
                CP_ASYNC16(sA + st * A_CHB + SMEM_SWZ(row * 128 + so),
                           Ag + (size_t)row * 6144 + ch * 128 + so);
            }
        };

        // zx prefetch (this step's gate slice) folded into group 0
        {
            const float* zsrc = zx + (size_t)t * B_SZ * G_SZ + (size_t)b0 * G_SZ + bn;
#pragma unroll
            for (int i = 0; i < 2; i++) {
                int seg = tid + i * 256;                  // 0..511
                int r = seg >> 5, c16 = (seg & 31) * 16;
                CP_ASYNC16(sZ + r * 512 + c16, (const char*)(zsrc + (size_t)r * G_SZ) + c16);
            }
        }
        loadA(0, 0); CP_COMMIT();
        loadA(1, 1); CP_COMMIT();

        for (int c = 0; c < PK_KCH; c++) {
            int n = c + 2;
            if (n < PK_KCH) loadA(n, n % PK_AST);
            CP_COMMIT();
            CP_WAIT2();
            __syncthreads();
            const uint32_t aT = sA + (c % PK_AST) * A_CHB;
            const uint32_t bT = sB + c * B_CHB;
#pragma unroll
            for (int k4 = 0; k4 < 4; k4++) {
                uint32_t af[2][4], bfr[4][2];
#pragma unroll
                for (int i = 0; i < 2; i++)
                    ldmx4(af[i], aT + SMEM_SWZ((a_row + i * 16) * 128 + k4 * 32 + a_k16));
#pragma unroll
                for (int jp = 0; jp < 2; jp++) {
                    uint32_t t4[4];
                    ldmx4(t4, bT + SMEM_SWZ((b_row + jp * 16) * 128 + k4 * 32 + b_k16));
                    bfr[2 * jp][0] = t4[0]; bfr[2 * jp][1] = t4[1];
                    bfr[2 * jp + 1][0] = t4[2]; bfr[2 * jp + 1][1] = t4[3];
                }
#pragma unroll
                for (int i = 0; i < 2; i++)
#pragma unroll
                    for (int j = 0; j < 4; j++)
                        mma16816(acc[i][j], af[i], bfr[j]);
            }
            __syncthreads();
        }

        // write split-K partials
#pragma unroll
        for (int i = 0; i < 2; i++) {
            const int r0 = wm * 32 + i * 16 + (lane >> 2);
#pragma unroll
            for (int j = 0; j < 4; j++) {
                const int col = bn + wn * 32 + j * 8 + (lane & 3) * 2;
                *(float2*)&zp[(size_t)r0 * G_SZ + col] = make_float2(acc[i][j][0], acc[i][j][1]);
                *(float2*)&zp[(size_t)(r0 + 8) * G_SZ + col] = make_float2(acc[i][j][2], acc[i][j][3]);
            }
        }

        // mini-barrier among the 4 K-split CTAs of this tile (all 4 wait)
        __threadfence();
        __syncthreads();
        if (tid == 0) {
            atomicAdd(&g_mini_cnt[tile], 1u);
            while (*(volatile unsigned*)&g_mini_cnt[tile] < 4u * (t + 1)) { }
        }
        __syncthreads();
        __threadfence();

        // gates: this CTA handles 16 batches x 32 units
        for (int it = tid; it < 512; it += 256) {
            int u_loc = it & 31, bl = it >> 5;
            int b = b0 + bl;
            int u = tile * 32 + u_loc;
            float4 z = *(const float4*)(zbuf + bl * 512 + u_loc * 16);
            size_t zo = (size_t)b * G_SZ + bn + u_loc * 4;
#pragma unroll
            for (int s = 0; s < PK_KS; s++) {
                float4 pz = *(const float4*)&g_zpart[s][zo];
                z.x += pz.x; z.y += pz.y; z.z += pz.z; z.w += pz.w;
            }
            int idx = b * H_SZ + u;
            float c_new = sigmoidf_(z.y) * g_c[idx] + sigmoidf_(z.x) * tanhf(z.z);
            float h_new = sigmoidf_(z.w) * tanhf(c_new);
            g_c[idx] = c_new;
            g_h[idx] = h_new;
            bf16 hi, lo; split2(h_new, hi, lo);
            bf16* ra = g_Ah + (size_t)b * 3072;
            ra[u] = hi; ra[H_SZ + u] = hi; ra[2 * H_SZ + u] = lo;
            bf16* rq = Aseq + ((size_t)b * T_SZ + t) * 3072 + u;
            rq[0] = hi; rq[H_SZ] = hi; rq[2 * H_SZ] = lo;
        }

        // full barrier (h visible to all before next step's A loads)
        __threadfence();
        __syncthreads();
        if (tid == 0) {
            atomicAdd(&g_full_cnt, 1u);
            while (*(volatile unsigned*)&g_full_cnt < (unsigned)PK_CTAS * (t + 1)) { }
        }
        __syncthreads();
        __threadfence();
    }
}

// ---------------- weight convert: W[K,N] -> B'[N,3K] = [hi|lo|hi] -----------
template <int PERMN>
__global__ __launch_bounds__(256) void conv_w(const float* __restrict__ W,
                                              bf16* __restrict__ Bp, int K, int N)
{
    __shared__ float tile[32][33];
    const int n0 = blockIdx.x * 32, k0 = blockIdx.y * 32;
    const int tx = threadIdx.x & 31, ty = threadIdx.x >> 5;
    for (int i = ty; i < 32; i += 8)
        tile[i][tx] = W[(size_t)(k0 + i) * N + n0 + tx];
    __syncthreads();
    for (int i = ty; i < 32; i += 8) {
        int n = n0 + i, k = k0 + tx;
        int np = PERMN ? ((n & 1023) * 4 + (n >> 10)) : n;
        bf16 hi, lo; split2(tile[tx][i], hi, lo);
        bf16* row = Bp + (size_t)np * 3 * K;
        row[k] = hi; row[K + k] = lo; row[2 * K + k] = hi;
    }
}

// ---------------- activation convert: X[M,K] -> A'[M,3K] = [hi|hi|lo] -------
__global__ __launch_bounds__(256) void conv_x(const float* __restrict__ X,
                                              bf16* __restrict__ Ap, int K, int total)
{
    int i = blockIdx.x * 256 + threadIdx.x;
    if (i >= total) return;
    int r = i / K, k = i - r * K;
    bf16 hi, lo; split2(X[i], hi, lo);
    bf16* row = Ap + (size_t)r * 3 * K;
    row[k] = hi; row[K + k] = hi; row[2 * K + k] = lo;
}

// ---------------- LayerNorm + ReLU -> split bf16 ----------------------------
__global__ __launch_bounds__(256) void ln_relu(const float* __restrict__ buf,
    const float* __restrict__ gamma, const float* __restrict__ beta,
    bf16* __restrict__ Ap)
{
    __shared__ float rs[8], rs2[8];
    const int row = blockIdx.x;
    const float* p = buf + (size_t)row * P_SZ;
    const int tid = threadIdx.x;
    float4 v = *(const float4*)&p[tid * 4];
    float s = v.x + v.y + v.z + v.w;
    float s2 = v.x * v.x + v.y * v.y + v.z * v.z + v.w * v.w;
#pragma unroll
    for (int off = 16; off > 0; off >>= 1) {
        s += __shfl_xor_sync(0xFFFFFFFFu, s, off);
        s2 += __shfl_xor_sync(0xFFFFFFFFu, s2, off);
    }
    if ((tid & 31) == 0) { rs[tid >> 5] = s; rs2[tid >> 5] = s2; }
    __syncthreads();
    float tot = 0.f, tot2 = 0.f;
#pragma unroll
    for (int i = 0; i < 8; i++) { tot += rs[i]; tot2 += rs2[i]; }
    const float mu = tot * (1.f / 1024.f);
    const float r = rsqrtf(tot2 * (1.f / 1024.f) - mu * mu + 1e-6f);
    float4 g = *(const float4*)&gamma[tid * 4];
    float4 b = *(const float4*)&beta[tid * 4];
    float o[4] = { fmaxf((v.x - mu) * r * g.x + b.x, 0.f),
                   fmaxf((v.y - mu) * r * g.y + b.y, 0.f),
                   fmaxf((v.z - mu) * r * g.z + b.z, 0.f),
                   fmaxf((v.w - mu) * r * g.w + b.w, 0.f) };
    bf16* rp = Ap + (size_t)row * 3 * P_SZ;
#pragma unroll
    for (int q = 0; q < 4; q++) {
        int k = tid * 4 + q;
        bf16 hi, lo; split2(o[q], hi, lo);
        rp[k] = hi; rp[P_SZ + k] = hi; rp[2 * P_SZ + k] = lo;
    }
}

// ---------------- state init / export ---------------------------------------
__global__ __launch_bounds__(256) void init_state(
    const float* __restrict__ c0, const float* __restrict__ h0)
{
    int i = blockIdx.x * 256 + threadIdx.x;       // 0 .. 64*1024-1
    int b = i >> 10, u = i & 1023;
    g_c[i] = c0[i];
    g_h[i] = h0[i];
    bf16 hi, lo; split2(h0[i], hi, lo);
    bf16* ra = g_Ah + (size_t)b * 3 * H_SZ;
    ra[u] = hi; ra[H_SZ + u] = hi; ra[2 * H_SZ + u] = lo;
    if (i == 0) {
        g_full_cnt = 0;
        for (int tle = 0; tle < PK_TILES; tle++) g_mini_cnt[tle] = 0;
    }
}
__global__ __launch_bounds__(256) void copy_out(float* dst_c, float* dst_h)
{
    int i = blockIdx.x * 256 + threadIdx.x;
    dst_c[i] = g_c[i];
    dst_h[i] = g_h[i];
}

// ---------------- launch -----------------------------------------------------
extern "C" void kernel_launch(void* const* d_in, const int* in_sizes, int n_in,
                              void* d_out, int out_size)
{
    const float* x        = (const float*)d_in[0];
    const float* c0       = (const float*)d_in[1];
    const float* h0       = (const float*)d_in[2];
    const float* W_pre    = (const float*)d_in[3];
    const float* b_pre    = (const float*)d_in[4];
    const float* ln_scale = (const float*)d_in[5];
    const float* ln_bias  = (const float*)d_in[6];
    const float* Wi0      = (const float*)d_in[7];
    const float* Wh0      = (const float*)d_in[8];
    const float* b0       = (const float*)d_in[9];
    const float* Wi1      = (const float*)d_in[10];
    const float* Wh1      = (const float*)d_in[11];
    const float* b1       = (const float*)d_in[12];
    const float* W_post   = (const float*)d_in[13];
    const float* b_post   = (const float*)d_in[14];
    const float* W_out    = (const float*)d_in[15];
    const float* b_out    = (const float*)d_in[16];
    float* out = (float*)d_out;

    float *pre_p, *zx_p;
    bf16 *Ax, *Aln, *As0, *As1, *Ahp;
    bf16 *Bpre, *Bwi0, *Bwh0, *Bwi1, *Bwh1, *Bpost, *Bout;
    cudaGetSymbolAddress((void**)&pre_p, g_pre);
    cudaGetSymbolAddress((void**)&zx_p, g_zx);
    cudaGetSymbolAddress((void**)&Ax, g_Ax);
    cudaGetSymbolAddress((void**)&Aln, g_Aln);
    cudaGetSymbolAddress((void**)&As0, g_Aseq0);
    cudaGetSymbolAddress((void**)&As1, g_Aseq1);
    cudaGetSymbolAddress((void**)&Ahp, g_Ahp);
    cudaGetSymbolAddress((void**)&Bpre, g_Bpre);
    cudaGetSymbolAddress((void**)&Bwi0, g_Bwi0);
    cudaGetSymbolAddress((void**)&Bwh0, g_Bwh0);
    cudaGetSymbolAddress((void**)&Bwi1, g_Bwi1);
    cudaGetSymbolAddress((void**)&Bwh1, g_Bwh1);
    cudaGetSymbolAddress((void**)&Bpost, g_Bpost);
    cudaGetSymbolAddress((void**)&Bout, g_Bout);

    const int SMEM_128_128 = S_ST * (128 + 128) * 128;               // 98304
    const int SMEM_128_32  = S_ST * (128 + 32) * 128;                // 61440
    const int SMEM_PK      = PK_KCH * B_CHB + PK_AST * A_CHB + Z_BUF; // 229376
    cudaFuncSetAttribute(gemm_mma<128, 128, 0>, cudaFuncAttributeMaxDynamicSharedMemorySize, SMEM_128_128);
    cudaFuncSetAttribute(gemm_mma<128, 128, 1>, cudaFuncAttributeMaxDynamicSharedMemorySize, SMEM_128_128);
    cudaFuncSetAttribute(gemm_mma<128, 128, 2>, cudaFuncAttributeMaxDynamicSharedMemorySize, SMEM_128_128);
    cudaFuncSetAttribute(gemm_mma<128, 32, 0>,  cudaFuncAttributeMaxDynamicSharedMemorySize, SMEM_128_32);
    cudaFuncSetAttribute(lstm_persistent,       cudaFuncAttributeMaxDynamicSharedMemorySize, SMEM_PK);

    // weight + input conversion
    conv_w<0><<<dim3(P_SZ / 32, F_SZ / 32), 256>>>(W_pre, Bpre, F_SZ, P_SZ);
    conv_w<0><<<dim3(G_SZ / 32, P_SZ / 32), 256>>>(Wi0, Bwi0, P_SZ, G_SZ);
    conv_w<1><<<dim3(G_SZ / 32, H_SZ / 32), 256>>>(Wh0, Bwh0, H_SZ, G_SZ);
    conv_w<0><<<dim3(G_SZ / 32, H_SZ / 32), 256>>>(Wi1, Bwi1, H_SZ, G_SZ);
    conv_w<1><<<dim3(G_SZ / 32, H_SZ / 32), 256>>>(Wh1, Bwh1, H_SZ, G_SZ);
    conv_w<0><<<dim3(P_SZ / 32, H_SZ / 32), 256>>>(W_post, Bpost, H_SZ, P_SZ);
    conv_w<0><<<dim3(A_SZ / 32, P_SZ / 32), 256>>>(W_out, Bout, P_SZ, A_SZ);
    conv_x<<<(R_SZ * F_SZ + 255) / 256, 256>>>(x, Ax, F_SZ, R_SZ * F_SZ);

    // pre dense -> fp32, then LN+relu -> split bf16
    gemm_mma<128, 128, 0><<<dim3(P_SZ / 128, R_SZ / 128), 256, SMEM_128_128>>>(
        Ax, Bpre, b_pre, pre_p, nullptr, P_SZ, 3 * F_SZ);
    ln_relu<<<R_SZ, 256>>>(pre_p, ln_scale, ln_bias, Aln);

    // layer-0 input gates (time-major, permuted cols)
    gemm_mma<128, 128, 1><<<dim3(G_SZ / 128, R_SZ / 128), 256, SMEM_128_128>>>(
        Aln, Bwi0, b0, zx_p, nullptr, G_SZ, 3 * P_SZ);

    init_state<<<256, 256>>>(c0, h0);
    lstm_persistent<<<PK_CTAS, 256, SMEM_PK>>>(Bwh0, zx_p, As0);
    copy_out<<<256, 256>>>(out, out + 2 * B_SZ * H_SZ);               // c1, h1

    // layer-1 input gates
    gemm_mma<128, 128, 1><<<dim3(G_SZ / 128, R_SZ / 128), 256, SMEM_128_128>>>(
        As0, Bwi1, b1, zx_p, nullptr, G_SZ, 3 * H_SZ);

    init_state<<<256, 256>>>(c0 + B_SZ * H_SZ, h0 + B_SZ * H_SZ);
    lstm_persistent<<<PK_CTAS, 256, SMEM_PK>>>(Bwh1, zx_p, As1);
    copy_out<<<256, 256>>>(out + B_SZ * H_SZ, out + 3 * B_SZ * H_SZ); // c2, h2

    // post dense + relu -> split bf16, then logits
    gemm_mma<128, 128, 2><<<dim3(P_SZ / 128, R_SZ / 128), 256, SMEM_128_128>>>(
        As1, Bpost, b_post, nullptr, Ahp, P_SZ, 3 * H_SZ);
    gemm_mma<128, 32, 0><<<dim3(1, R_SZ / 128), 256, SMEM_128_32>>>(
        Ahp, Bout, b_out, out + 4 * B_SZ * H_SZ, nullptr, A_SZ, 3 * P_SZ);
}

// round 11
// speedup vs baseline: 1.1088x; 1.1088x over previous
#include <cuda_runtime.h>
#include <cuda_bf16.h>
#include <math.h>
#include <stdint.h>

#define B_SZ 64
#define T_SZ 128
#define F_SZ 512
#define H_SZ 1024
#define P_SZ 1024
#define A_SZ 32
#define R_SZ 8192
#define G_SZ 4096
#define S_ST 3          /* cp.async pipeline stages */
#define KSPLIT 4
#define LS_TILES 32
#define LS_KCH 12       /* 12 chunks of 64 over K-slice of 768 */

typedef __nv_bfloat16 bf16;

// ---------------- scratch (static device globals) ---------------------------
__device__ float g_pre[(size_t)R_SZ * P_SZ];
__device__ float g_zx[(size_t)R_SZ * G_SZ];              // time-major [T][B][4H-permuted]
__device__ float g_zpart[KSPLIT][(size_t)B_SZ * G_SZ];   // split-K partials (permuted cols)
__device__ float g_c[B_SZ * H_SZ];
__device__ float g_h[B_SZ * H_SZ];
__device__ unsigned g_tile_cnt[LS_TILES];                // monotonic last-arrival counters

__device__ __align__(256) bf16 g_Ax  [(size_t)R_SZ * 3 * F_SZ];
__device__ __align__(256) bf16 g_Aln [(size_t)R_SZ * 3 * P_SZ];
__device__ __align__(256) bf16 g_Aseq0[(size_t)R_SZ * 3 * H_SZ];
__device__ __align__(256) bf16 g_Aseq1[(size_t)R_SZ * 3 * H_SZ];
__device__ __align__(256) bf16 g_Ahp [(size_t)R_SZ * 3 * P_SZ];
__device__ __align__(256) bf16 g_Ah  [B_SZ * 3 * H_SZ];

__device__ __align__(256) bf16 g_Bpre [(size_t)P_SZ * 3 * F_SZ];
__device__ __align__(256) bf16 g_Bwi0 [(size_t)G_SZ * 3 * P_SZ];
__device__ __align__(256) bf16 g_Bwh0 [(size_t)G_SZ * 3 * H_SZ];   // N-permuted
__device__ __align__(256) bf16 g_Bwi1 [(size_t)G_SZ * 3 * H_SZ];
__device__ __align__(256) bf16 g_Bwh1 [(size_t)G_SZ * 3 * H_SZ];   // N-permuted
__device__ __align__(256) bf16 g_Bpost[(size_t)P_SZ * 3 * H_SZ];
__device__ __align__(256) bf16 g_Bout [(size_t)A_SZ * 3 * P_SZ];

// ---------------- helpers ---------------------------------------------------
__device__ __forceinline__ uint32_t smem_u32(const void* p) {
    uint32_t a;
    asm("{ .reg .u64 t; cvta.to.shared.u64 t, %1; cvt.u32.u64 %0, t; }" : "=r"(a) : "l"(p));
    return a;
}
#define SMEM_SWZ(o) ((o) ^ (((o) >> 3) & 0x70))
#define CP_ASYNC16(dst, src) \
    asm volatile("cp.async.cg.shared.global [%0], [%1], 16;" :: "r"(dst), "l"(src))
#define CP_COMMIT() asm volatile("cp.async.commit_group;" ::: "memory")
#define CP_WAIT2()  asm volatile("cp.async.wait_group 2;" ::: "memory")

__device__ __forceinline__ void ldmx4(uint32_t* r, uint32_t addr) {
    asm volatile("ldmatrix.sync.aligned.m8n8.x4.shared.b16 {%0,%1,%2,%3}, [%4];"
                 : "=r"(r[0]), "=r"(r[1]), "=r"(r[2]), "=r"(r[3]) : "r"(addr));
}
__device__ __forceinline__ void mma16816(float* c, const uint32_t* a, const uint32_t* b) {
    asm volatile("mma.sync.aligned.m16n8k16.row.col.f32.bf16.bf16.f32 "
                 "{%0,%1,%2,%3}, {%4,%5,%6,%7}, {%8,%9}, {%0,%1,%2,%3};"
                 : "+f"(c[0]), "+f"(c[1]), "+f"(c[2]), "+f"(c[3])
                 : "r"(a[0]), "r"(a[1]), "r"(a[2]), "r"(a[3]), "r"(b[0]), "r"(b[1]));
}
__device__ __forceinline__ void split2(float v, bf16& hi, bf16& lo) {
    hi = __float2bfloat16_rn(v);
    lo = __float2bfloat16_rn(v - __bfloat162float(hi));
}
__device__ __forceinline__ float sigmoidf_(float x) { return 1.f / (1.f + expf(-x)); }

// ---------------- big HMMA GEMM (feed-forward ops) ---------------------------
// OUTMODE 0: fp32 row-major (+bias). 1: fp32 time-major [T][B][N] PERMUTED cols.
//         2: bf16-split [M, 3*Ntot] (+bias, relu).
template <int BM, int BN, int OUTMODE>
__global__ __launch_bounds__(256, 1) void gemm_mma(
    const bf16* __restrict__ Ap, const bf16* __restrict__ Bp,
    const float* __restrict__ bias, float* __restrict__ Cf,
    bf16* __restrict__ Cb, int Ntot, int K3)
{
    constexpr int WM = (BN == 32) ? 4 : 2;
    constexpr int WN = 8 / WM;
    constexpr int TM = BM / WM;
    constexpr int TN = BN / WN;
    constexpr int MT = TM / 16;
    constexpr int NT = TN / 8;
    constexpr int ABYTES = BM * 128;
    constexpr int BBYTES = BN * 128;

    extern __shared__ __align__(1024) char smem[];
    const uint32_t sA = smem_u32(smem);
    const uint32_t sB = sA + S_ST * ABYTES;

    const int tid = threadIdx.x;
    const int lane = tid & 31, wid = tid >> 5;
    const int wm = wid % WM, wn = wid / WM;
    const int bm = blockIdx.y * BM;
    const int bn = blockIdx.x * BN;
    const int NC = K3 / 64;

    const char* Ag = (const char*)(Ap + (size_t)bm * K3);
    const char* Bg = (const char*)(Bp + (size_t)bn * K3);
    const size_t rowB = (size_t)K3 * 2;

    float acc[MT][NT][4];
#pragma unroll
    for (int i = 0; i < MT; i++)
#pragma unroll
        for (int j = 0; j < NT; j++)
#pragma unroll
            for (int q = 0; q < 4; q++) acc[i][j][q] = 0.f;

    auto load_chunk = [&](int c, int stage) {
        const size_t coff = (size_t)c * 128;
        const uint32_t aT = sA + stage * ABYTES;
        const uint32_t bT = sB + stage * BBYTES;
#pragma unroll
        for (int i = 0; i < BM / 32; i++) {
            int seg = tid + i * 256, row = seg >> 3, so = (seg & 7) * 16;
            CP_ASYNC16(aT + SMEM_SWZ(row * 128 + so), Ag + (size_t)row * rowB + coff + so);
        }
#pragma unroll
        for (int i = 0; i < BN / 32; i++) {
            int seg = tid + i * 256, row = seg >> 3, so = (seg & 7) * 16;
            CP_ASYNC16(bT + SMEM_SWZ(row * 128 + so), Bg + (size_t)row * rowB + coff + so);
        }
    };

    load_chunk(0, 0); CP_COMMIT();
    load_chunk(1, 1); CP_COMMIT();

    const int a_row = wm * TM + (lane & 15);
    const int a_k16 = (lane >> 4) * 16;
    const int b_row = wn * TN + (lane & 7) + ((lane >> 4) << 3);
    const int b_k16 = ((lane >> 3) & 1) * 16;

    for (int c = 0; c < NC; c++) {
        int n = c + 2;
        if (n < NC) load_chunk(n, n % S_ST);
        CP_COMMIT();
        CP_WAIT2();
        __syncthreads();

        const uint32_t aT = sA + (c % S_ST) * ABYTES;
        const uint32_t bT = sB + (c % S_ST) * BBYTES;
#pragma unroll
        for (int ks = 0; ks < 4; ks++) {
            uint32_t af[MT][4], bfr[NT][2];
#pragma unroll
            for (int i = 0; i < MT; i++)
                ldmx4(af[i], aT + SMEM_SWZ((a_row + i * 16) * 128 + ks * 32 + a_k16));
#pragma unroll
            for (int jp = 0; jp < NT / 2; jp++) {
                uint32_t t4[4];
                ldmx4(t4, bT + SMEM_SWZ((b_row + jp * 16) * 128 + ks * 32 + b_k16));
                bfr[2 * jp][0] = t4[0]; bfr[2 * jp][1] = t4[1];
                bfr[2 * jp + 1][0] = t4[2]; bfr[2 * jp + 1][1] = t4[3];
            }
#pragma unroll
            for (int i = 0; i < MT; i++)
#pragma unroll
                for (int j = 0; j < NT; j++)
                    mma16816(acc[i][j], af[i], bfr[j]);
        }
        __syncthreads();
    }

#pragma unroll
    for (int i = 0; i < MT; i++) {
        const int r0 = bm + wm * TM + i * 16 + (lane >> 2);
        const int r1 = r0 + 8;
#pragma unroll
        for (int j = 0; j < NT; j++) {
            const int col = bn + wn * TN + j * 8 + (lane & 3) * 2;
            const float2 bv = *(const float2*)&bias[col];
            float v00 = acc[i][j][0] + bv.x, v01 = acc[i][j][1] + bv.y;
            float v10 = acc[i][j][2] + bv.x, v11 = acc[i][j][3] + bv.y;
            if (OUTMODE == 0) {
                *(float2*)&Cf[(size_t)r0 * Ntot + col] = make_float2(v00, v01);
                *(float2*)&Cf[(size_t)r1 * Ntot + col] = make_float2(v10, v11);
            } else if (OUTMODE == 1) {
                int b0i = r0 >> 7, t0 = r0 & 127, b1i = r1 >> 7, t1 = r1 & 127;
                int c0p = (col & 1023) * 4 + (col >> 10);
                int c1p = ((col + 1) & 1023) * 4 + ((col + 1) >> 10);
                float* q0 = Cf + ((size_t)t0 * B_SZ + b0i) * Ntot;
                float* q1 = Cf + ((size_t)t1 * B_SZ + b1i) * Ntot;
                q0[c0p] = v00; q0[c1p] = v01;
                q1[c0p] = v10; q1[c1p] = v11;
            } else {
                v00 = fmaxf(v00, 0.f); v01 = fmaxf(v01, 0.f);
                v10 = fmaxf(v10, 0.f); v11 = fmaxf(v11, 0.f);
                bf16 h0, l0, h1, l1;
                bf16* row0 = Cb + (size_t)r0 * 3 * Ntot;
                bf16* row1 = Cb + (size_t)r1 * 3 * Ntot;
                split2(v00, h0, l0); split2(v01, h1, l1);
                *(__nv_bfloat162*)&row0[col] = __nv_bfloat162(h0, h1);
                *(__nv_bfloat162*)&row0[Ntot + col] = __nv_bfloat162(h0, h1);
                *(__nv_bfloat162*)&row0[2 * Ntot + col] = __nv_bfloat162(l0, l1);
                split2(v10, h0, l0); split2(v11, h1, l1);
                *(__nv_bfloat162*)&row1[col] = __nv_bfloat162(h0, h1);
                *(__nv_bfloat162*)&row1[Ntot + col] = __nv_bfloat162(h0, h1);
                *(__nv_bfloat162*)&row1[2 * Ntot + col] = __nv_bfloat162(l0, l1);
            }
        }
    }
}

// ---------------- fused LSTM step: split-K GEMM + last-arrival gates --------
// grid (32 tiles, 1, 4 K-splits). Tile owns 128 permuted cols = 32 units.
__global__ __launch_bounds__(256, 1) void lstm_step(
    const bf16* __restrict__ Bwh, const float* __restrict__ zx,
    bf16* __restrict__ Aseq, int t)
{
    constexpr int ABYTES = 64 * 128;     // 8 KB
    constexpr int BBYTES = 128 * 128;    // 16 KB
    extern __shared__ __align__(1024) char smem[];
    const uint32_t sA = smem_u32(smem);
    const uint32_t sB = sA + S_ST * ABYTES;

    const int tid = threadIdx.x;
    const int lane = tid & 31, wid = tid >> 5;
    const int tile = blockIdx.x;
    const int ks = blockIdx.z;
    const int wm = wid & 1, wn = wid >> 1;      // TM=32, TN=32, MT=2, NT=4
    const int bn = tile * 128;
    const size_t rowB = 3072 * 2;               // 6144 B per B' row

    const char* Ag = (const char*)g_Ah + ks * 1536;
    const char* Bg = (const char*)Bwh + (size_t)bn * rowB + ks * 1536;
    float* zp = g_zpart[ks];

    float acc[2][4][4];
#pragma unroll
    for (int i = 0; i < 2; i++)
#pragma unroll
        for (int j = 0; j < 4; j++)
#pragma unroll
            for (int q = 0; q < 4; q++) acc[i][j][q] = 0.f;

    auto load_chunk = [&](int c, int stage) {
        const size_t coff = (size_t)c * 128;
        const uint32_t aT = sA + stage * ABYTES;
        const uint32_t bT = sB + stage * BBYTES;
#pragma unroll
        for (int i = 0; i < 2; i++) {          // A: 64 rows x 8 segs = 512
            int seg = tid + i * 256, row = seg >> 3, so = (seg & 7) * 16;
            CP_ASYNC16(aT + SMEM_SWZ(row * 128 + so), Ag + (size_t)row * 6144 + coff + so);
        }
#pragma unroll
        for (int i = 0; i < 4; i++) {          // B: 128 rows x 8 segs = 1024
            int seg = tid + i * 256, row = seg >> 3, so = (seg & 7) * 16;
            CP_ASYNC16(bT + SMEM_SWZ(row * 128 + so), Bg + (size_t)row * rowB + coff + so);
        }
    };

    load_chunk(0, 0); CP_COMMIT();
    load_chunk(1, 1); CP_COMMIT();

    const int a_row = wm * 32 + (lane & 15);
    const int a_k16 = (lane >> 4) * 16;
    const int b_row = wn * 32 + (lane & 7) + ((lane >> 4) << 3);
    const int b_k16 = ((lane >> 3) & 1) * 16;

    for (int c = 0; c < LS_KCH; c++) {
        int n = c + 2;
        if (n < LS_KCH) load_chunk(n, n % S_ST);
        CP_COMMIT();
        CP_WAIT2();
        __syncthreads();
        const uint32_t aT = sA + (c % S_ST) * ABYTES;
        const uint32_t bT = sB + (c % S_ST) * BBYTES;
#pragma unroll
        for (int k4 = 0; k4 < 4; k4++) {
            uint32_t af[2][4], bfr[4][2];
#pragma unroll
            for (int i = 0; i < 2; i++)
                ldmx4(af[i], aT + SMEM_SWZ((a_row + i * 16) * 128 + k4 * 32 + a_k16));
#pragma unroll
            for (int jp = 0; jp < 2; jp++) {
                uint32_t t4[4];
                ldmx4(t4, bT + SMEM_SWZ((b_row + jp * 16) * 128 + k4 * 32 + b_k16));
                bfr[2 * jp][0] = t4[0]; bfr[2 * jp][1] = t4[1];
                bfr[2 * jp + 1][0] = t4[2]; bfr[2 * jp + 1][1] = t4[3];
            }
#pragma unroll
            for (int i = 0; i < 2; i++)
#pragma unroll
                for (int j = 0; j < 4; j++)
                    mma16816(acc[i][j], af[i], bfr[j]);
        }
        __syncthreads();
    }

    // write split-K partials
#pragma unroll
    for (int i = 0; i < 2; i++) {
        const int r0 = wm * 32 + i * 16 + (lane >> 2);
#pragma unroll
        for (int j = 0; j < 4; j++) {
            const int col = bn + wn * 32 + j * 8 + (lane & 3) * 2;
            *(float2*)&zp[(size_t)r0 * G_SZ + col] = make_float2(acc[i][j][0], acc[i][j][1]);
            *(float2*)&zp[(size_t)(r0 + 8) * G_SZ + col] = make_float2(acc[i][j][2], acc[i][j][3]);
        }
    }

    // last-arrival detection (no spinning)
    __threadfence();
    __syncthreads();
    __shared__ unsigned s_old;
    if (tid == 0) s_old = atomicAdd(&g_tile_cnt[tile], 1u);
    __syncthreads();
    if (s_old != (unsigned)(KSPLIT * (t + 1) - 1)) return;
    __threadfence();

    // gates for this tile: 64 batches x 32 units (2048 items, 8 per thread)
    const float* zx_t = zx + (size_t)t * B_SZ * G_SZ;
    for (int it = tid; it < 2048; it += 256) {
        int u_loc = it & 31, b = it >> 5;
        int u = tile * 32 + u_loc;
        size_t zo = (size_t)b * G_SZ + bn + u_loc * 4;
        float4 z = *(const float4*)&zx_t[zo];
#pragma unroll
        for (int s = 0; s < KSPLIT; s++) {
            float4 pz = *(const float4*)&g_zpart[s][zo];
            z.x += pz.x; z.y += pz.y; z.z += pz.z; z.w += pz.w;
        }
        int idx = b * H_SZ + u;
        float c_new = sigmoidf_(z.y) * g_c[idx] + sigmoidf_(z.x) * tanhf(z.z);
        float h_new = sigmoidf_(z.w) * tanhf(c_new);
        g_c[idx] = c_new;
        g_h[idx] = h_new;
        bf16 hi, lo; split2(h_new, hi, lo);
        bf16* ra = g_Ah + (size_t)b * 3072;
        ra[u] = hi; ra[H_SZ + u] = hi; ra[2 * H_SZ + u] = lo;
        bf16* rq = Aseq + ((size_t)b * T_SZ + t) * 3072 + u;
        rq[0] = hi; rq[H_SZ] = hi; rq[2 * H_SZ] = lo;
    }
}

// ---------------- weight convert: W[K,N] -> B'[N,3K] = [hi|lo|hi] -----------
template <int PERMN>
__global__ __launch_bounds__(256) void conv_w(const float* __restrict__ W,
                                              bf16* __restrict__ Bp, int K, int N)
{
    __shared__ float tile[32][33];
    const int n0 = blockIdx.x * 32, k0 = blockIdx.y * 32;
    const int tx = threadIdx.x & 31, ty = threadIdx.x >> 5;
    for (int i = ty; i < 32; i += 8)
        tile[i][tx] = W[(size_t)(k0 + i) * N + n0 + tx];
    __syncthreads();
    for (int i = ty; i < 32; i += 8) {
        int n = n0 + i, k = k0 + tx;
        int np = PERMN ? ((n & 1023) * 4 + (n >> 10)) : n;
        bf16 hi, lo; split2(tile[tx][i], hi, lo);
        bf16* row = Bp + (size_t)np * 3 * K;
        row[k] = hi; row[K + k] = lo; row[2 * K + k] = hi;
    }
}

// ---------------- activation convert: X[M,K] -> A'[M,3K] = [hi|hi|lo] -------
__global__ __launch_bounds__(256) void conv_x(const float* __restrict__ X,
                                              bf16* __restrict__ Ap, int K, int total)
{
    int i = blockIdx.x * 256 + threadIdx.x;
    if (i >= total) return;
    int r = i / K, k = i - r * K;
    bf16 hi, lo; split2(X[i], hi, lo);
    bf16* row = Ap + (size_t)r * 3 * K;
    row[k] = hi; row[K + k] = hi; row[2 * K + k] = lo;
}

// ---------------- LayerNorm + ReLU -> split bf16 ----------------------------
__global__ __launch_bounds__(256) void ln_relu(const float* __restrict__ buf,
    const float* __restrict__ gamma, const float* __restrict__ beta,
    bf16* __restrict__ Ap)
{
    __shared__ float rs[8], rs2[8];
    const int row = blockIdx.x;
    const float* p = buf + (size_t)row * P_SZ;
    const int tid = threadIdx.x;
    float4 v = *(const float4*)&p[tid * 4];
    float s = v.x + v.y + v.z + v.w;
    float s2 = v.x * v.x + v.y * v.y + v.z * v.z + v.w * v.w;
#pragma unroll
    for (int off = 16; off > 0; off >>= 1) {
        s += __shfl_xor_sync(0xFFFFFFFFu, s, off);
        s2 += __shfl_xor_sync(0xFFFFFFFFu, s2, off);
    }
    if ((tid & 31) == 0) { rs[tid >> 5] = s; rs2[tid >> 5] = s2; }
    __syncthreads();
    float tot = 0.f, tot2 = 0.f;
#pragma unroll
    for (int i = 0; i < 8; i++) { tot += rs[i]; tot2 += rs2[i]; }
    const float mu = tot * (1.f / 1024.f);
    const float r = rsqrtf(tot2 * (1.f / 1024.f) - mu * mu + 1e-6f);
    float4 g = *(const float4*)&gamma[tid * 4];
    float4 b = *(const float4*)&beta[tid * 4];
    float o[4] = { fmaxf((v.x - mu) * r * g.x + b.x, 0.f),
                   fmaxf((v.y - mu) * r * g.y + b.y, 0.f),
                   fmaxf((v.z - mu) * r * g.z + b.z, 0.f),
                   fmaxf((v.w - mu) * r * g.w + b.w, 0.f) };
    bf16* rp = Ap + (size_t)row * 3 * P_SZ;
#pragma unroll
    for (int q = 0; q < 4; q++) {
        int k = tid * 4 + q;
        bf16 hi, lo; split2(o[q], hi, lo);
        rp[k] = hi; rp[P_SZ + k] = hi; rp[2 * P_SZ + k] = lo;
    }
}

// ---------------- state init / export ---------------------------------------
__global__ __launch_bounds__(256) void init_state(
    const float* __restrict__ c0, const float* __restrict__ h0)
{
    int i = blockIdx.x * 256 + threadIdx.x;       // 0 .. 64*1024-1
    int b = i >> 10, u = i & 1023;
    g_c[i] = c0[i];
    g_h[i] = h0[i];
    bf16 hi, lo; split2(h0[i], hi, lo);
    bf16* ra = g_Ah + (size_t)b * 3 * H_SZ;
    ra[u] = hi; ra[H_SZ + u] = hi; ra[2 * H_SZ + u] = lo;
    if (i < LS_TILES) g_tile_cnt[i] = 0;
}
__global__ __launch_bounds__(256) void copy_out(float* dst_c, float* dst_h)
{
    int i = blockIdx.x * 256 + threadIdx.x;
    dst_c[i] = g_c[i];
    dst_h[i] = g_h[i];
}

// ---------------- launch -----------------------------------------------------
extern "C" void kernel_launch(void* const* d_in, const int* in_sizes, int n_in,
                              void* d_out, int out_size)
{
    const float* x        = (const float*)d_in[0];
    const float* c0       = (const float*)d_in[1];
    const float* h0       = (const float*)d_in[2];
    const float* W_pre    = (const float*)d_in[3];
    const float* b_pre    = (const float*)d_in[4];
    const float* ln_scale = (const float*)d_in[5];
    const float* ln_bias  = (const float*)d_in[6];
    const float* Wi0      = (const float*)d_in[7];
    const float* Wh0      = (const float*)d_in[8];
    const float* b0       = (const float*)d_in[9];
    const float* Wi1      = (const float*)d_in[10];
    const float* Wh1      = (const float*)d_in[11];
    const float* b1       = (const float*)d_in[12];
    const float* W_post   = (const float*)d_in[13];
    const float* b_post   = (const float*)d_in[14];
    const float* W_out    = (const float*)d_in[15];
    const float* b_out    = (const float*)d_in[16];
    float* out = (float*)d_out;

    float *pre_p, *zx_p;
    bf16 *Ax, *Aln, *As0, *As1, *Ahp;
    bf16 *Bpre, *Bwi0, *Bwh0, *Bwi1, *Bwh1, *Bpost, *Bout;
    cudaGetSymbolAddress((void**)&pre_p, g_pre);
    cudaGetSymbolAddress((void**)&zx_p, g_zx);
    cudaGetSymbolAddress((void**)&Ax, g_Ax);
    cudaGetSymbolAddress((void**)&Aln, g_Aln);
    cudaGetSymbolAddress((void**)&As0, g_Aseq0);
    cudaGetSymbolAddress((void**)&As1, g_Aseq1);
    cudaGetSymbolAddress((void**)&Ahp, g_Ahp);
    cudaGetSymbolAddress((void**)&Bpre, g_Bpre);
    cudaGetSymbolAddress((void**)&Bwi0, g_Bwi0);
    cudaGetSymbolAddress((void**)&Bwh0, g_Bwh0);
    cudaGetSymbolAddress((void**)&Bwi1, g_Bwi1);
    cudaGetSymbolAddress((void**)&Bwh1, g_Bwh1);
    cudaGetSymbolAddress((void**)&Bpost, g_Bpost);
    cudaGetSymbolAddress((void**)&Bout, g_Bout);

    const int SMEM_128_128 = S_ST * (128 + 128) * 128;   // 98304
    const int SMEM_128_32  = S_ST * (128 + 32) * 128;    // 61440
    const int SMEM_LS      = S_ST * (64 + 128) * 128;    // 73728
    cudaFuncSetAttribute(gemm_mma<128, 128, 0>, cudaFuncAttributeMaxDynamicSharedMemorySize, SMEM_128_128);
    cudaFuncSetAttribute(gemm_mma<128, 128, 1>, cudaFuncAttributeMaxDynamicSharedMemorySize, SMEM_128_128);
    cudaFuncSetAttribute(gemm_mma<128, 128, 2>, cudaFuncAttributeMaxDynamicSharedMemorySize, SMEM_128_128);
    cudaFuncSetAttribute(gemm_mma<128, 32, 0>,  cudaFuncAttributeMaxDynamicSharedMemorySize, SMEM_128_32);
    cudaFuncSetAttribute(lstm_step,             cudaFuncAttributeMaxDynamicSharedMemorySize, SMEM_LS);

    // weight + input conversion
    conv_w<0><<<dim3(P_SZ / 32, F_SZ / 32), 256>>>(W_pre, Bpre, F_SZ, P_SZ);
    conv_w<0><<<dim3(G_SZ / 32, P_SZ / 32), 256>>>(Wi0, Bwi0, P_SZ, G_SZ);
    conv_w<1><<<dim3(G_SZ / 32, H_SZ / 32), 256>>>(Wh0, Bwh0, H_SZ, G_SZ);
    conv_w<0><<<dim3(G_SZ / 32, H_SZ / 32), 256>>>(Wi1, Bwi1, H_SZ, G_SZ);
    conv_w<1><<<dim3(G_SZ / 32, H_SZ / 32), 256>>>(Wh1, Bwh1, H_SZ, G_SZ);
    conv_w<0><<<dim3(P_SZ / 32, H_SZ / 32), 256>>>(W_post, Bpost, H_SZ, P_SZ);
    conv_w<0><<<dim3(A_SZ / 32, P_SZ / 32), 256>>>(W_out, Bout, P_SZ, A_SZ);
    conv_x<<<(R_SZ * F_SZ + 255) / 256, 256>>>(x, Ax, F_SZ, R_SZ * F_SZ);

    // pre dense -> fp32, then LN+relu -> split bf16
    gemm_mma<128, 128, 0><<<dim3(P_SZ / 128, R_SZ / 128), 256, SMEM_128_128>>>(
        Ax, Bpre, b_pre, pre_p, nullptr, P_SZ, 3 * F_SZ);
    ln_relu<<<R_SZ, 256>>>(pre_p, ln_scale, ln_bias, Aln);

    // layer-0 input gates (time-major, permuted cols)
    gemm_mma<128, 128, 1><<<dim3(G_SZ / 128, R_SZ / 128), 256, SMEM_128_128>>>(
        Aln, Bwi0, b0, zx_p, nullptr, G_SZ, 3 * P_SZ);

    init_state<<<256, 256>>>(c0, h0);
    for (int t = 0; t < T_SZ; t++)
        lstm_step<<<dim3(LS_TILES, 1, KSPLIT), 256, SMEM_LS>>>(Bwh0, zx_p, As0, t);
    copy_out<<<256, 256>>>(out, out + 2 * B_SZ * H_SZ);               // c1, h1

    // layer-1 input gates
    gemm_mma<128, 128, 1><<<dim3(G_SZ / 128, R_SZ / 128), 256, SMEM_128_128>>>(
        As0, Bwi1, b1, zx_p, nullptr, G_SZ, 3 * H_SZ);

    init_state<<<256, 256>>>(c0 + B_SZ * H_SZ, h0 + B_SZ * H_SZ);
    for (int t = 0; t < T_SZ; t++)
        lstm_step<<<dim3(LS_TILES, 1, KSPLIT), 256, SMEM_LS>>>(Bwh1, zx_p, As1, t);
    copy_out<<<256, 256>>>(out + B_SZ * H_SZ, out + 3 * B_SZ * H_SZ); // c2, h2

    // post dense + relu -> split bf16, then logits
    gemm_mma<128, 128, 2><<<dim3(P_SZ / 128, R_SZ / 128), 256, SMEM_128_128>>>(
        As1, Bpost, b_post, nullptr, Ahp, P_SZ, 3 * H_SZ);
    gemm_mma<128, 32, 0><<<dim3(1, R_SZ / 128), 256, SMEM_128_32>>>(
        Ahp, Bout, b_out, out + 4 * B_SZ * H_SZ, nullptr, A_SZ, 3 * P_SZ);
}

// round 13
// speedup vs baseline: 1.6828x; 1.5177x over previous
#include <cuda_runtime.h>
#include <cuda_bf16.h>
#include <math.h>
#include <stdint.h>

#define B_SZ 64
#define T_SZ 128
#define F_SZ 512
#define H_SZ 1024
#define P_SZ 1024
#define A_SZ 32
#define R_SZ 8192
#define G_SZ 4096
#define S_ST 3          /* cp.async pipeline stages */

typedef __nv_bfloat16 bf16;

// ---------------- scratch (static device globals) ---------------------------
__device__ float g_pre[(size_t)R_SZ * P_SZ];
__device__ float g_zx[(size_t)R_SZ * G_SZ];          // L0 input preacts [T][B][4H-perm]
__device__ float g_zpA[3][B_SZ * G_SZ];              // L0 split-K partials
__device__ float g_zpB[6][B_SZ * G_SZ];              // L1 split-K partials
__device__ float g_cst[2 * B_SZ * H_SZ];             // c state (both layers)
__device__ float g_hst[2 * B_SZ * H_SZ];             // h state fp32 (for output)

__device__ __align__(256) bf16 g_Acat[B_SZ * 6144];  // [h0_split(3072) | h1_split(3072)]
__device__ __align__(256) bf16 g_Ax  [(size_t)R_SZ * 3 * F_SZ];
__device__ __align__(256) bf16 g_Aln [(size_t)R_SZ * 3 * P_SZ];
__device__ __align__(256) bf16 g_Aseq1[(size_t)R_SZ * 3 * H_SZ];
__device__ __align__(256) bf16 g_Ahp [(size_t)R_SZ * 3 * P_SZ];

__device__ __align__(256) bf16 g_Bpre [(size_t)P_SZ * 3 * F_SZ];
__device__ __align__(256) bf16 g_Bwi0 [(size_t)G_SZ * 3 * P_SZ];
__device__ __align__(256) bf16 g_Bwh0 [(size_t)G_SZ * 3 * H_SZ];   // N-permuted
__device__ __align__(256) bf16 g_Bcat1[(size_t)G_SZ * 6144];       // N-perm [Wi1'|Wh1']
__device__ __align__(256) bf16 g_Bpost[(size_t)P_SZ * 3 * H_SZ];
__device__ __align__(256) bf16 g_Bout [(size_t)A_SZ * 3 * P_SZ];

// ---------------- helpers ---------------------------------------------------
__device__ __forceinline__ uint32_t smem_u32(const void* p) {
    uint32_t a;
    asm("{ .reg .u64 t; cvta.to.shared.u64 t, %1; cvt.u32.u64 %0, t; }" : "=r"(a) : "l"(p));
    return a;
}
#define SMEM_SWZ(o) ((o) ^ (((o) >> 3) & 0x70))
#define CP_ASYNC16(dst, src) \
    asm volatile("cp.async.cg.shared.global [%0], [%1], 16;" :: "r"(dst), "l"(src))
#define CP_COMMIT() asm volatile("cp.async.commit_group;" ::: "memory")
#define CP_WAIT2()  asm volatile("cp.async.wait_group 2;" ::: "memory")

__device__ __forceinline__ void ldmx4(uint32_t* r, uint32_t addr) {
    asm volatile("ldmatrix.sync.aligned.m8n8.x4.shared.b16 {%0,%1,%2,%3}, [%4];"
                 : "=r"(r[0]), "=r"(r[1]), "=r"(r[2]), "=r"(r[3]) : "r"(addr));
}
__device__ __forceinline__ void mma16816(float* c, const uint32_t* a, const uint32_t* b) {
    asm volatile("mma.sync.aligned.m16n8k16.row.col.f32.bf16.bf16.f32 "
                 "{%0,%1,%2,%3}, {%4,%5,%6,%7}, {%8,%9}, {%0,%1,%2,%3};"
                 : "+f"(c[0]), "+f"(c[1]), "+f"(c[2]), "+f"(c[3])
                 : "r"(a[0]), "r"(a[1]), "r"(a[2]), "r"(a[3]), "r"(b[0]), "r"(b[1]));
}
__device__ __forceinline__ void split2(float v, bf16& hi, bf16& lo) {
    hi = __float2bfloat16_rn(v);
    lo = __float2bfloat16_rn(v - __bfloat162float(hi));
}
__device__ __forceinline__ float sigmoidf_(float x) { return 1.f / (1.f + expf(-x)); }

// ---------------- big HMMA GEMM (feed-forward ops) ---------------------------
// OUTMODE 0: fp32 row-major (+bias). 1: fp32 time-major [T][B][N] PERMUTED cols.
//         2: bf16-split [M, 3*Ntot] (+bias, relu).
template <int BM, int BN, int OUTMODE>
__global__ __launch_bounds__(256, 1) void gemm_mma(
    const bf16* __restrict__ Ap, const bf16* __restrict__ Bp,
    const float* __restrict__ bias, float* __restrict__ Cf,
    bf16* __restrict__ Cb, int Ntot, int K3)
{
    constexpr int WM = (BN == 32) ? 4 : 2;
    constexpr int WN = 8 / WM;
    constexpr int TM = BM / WM;
    constexpr int TN = BN / WN;
    constexpr int MT = TM / 16;
    constexpr int NT = TN / 8;
    constexpr int ABYTES = BM * 128;
    constexpr int BBYTES = BN * 128;

    extern __shared__ __align__(1024) char smem[];
    const uint32_t sA = smem_u32(smem);
    const uint32_t sB = sA + S_ST * ABYTES;

    const int tid = threadIdx.x;
    const int lane = tid & 31, wid = tid >> 5;
    const int wm = wid % WM, wn = wid / WM;
    const int bm = blockIdx.y * BM;
    const int bn = blockIdx.x * BN;
    const int NC = K3 / 64;

    const char* Ag = (const char*)(Ap + (size_t)bm * K3);
    const char* Bg = (const char*)(Bp + (size_t)bn * K3);
    const size_t rowB = (size_t)K3 * 2;

    float acc[MT][NT][4];
#pragma unroll
    for (int i = 0; i < MT; i++)
#pragma unroll
        for (int j = 0; j < NT; j++)
#pragma unroll
            for (int q = 0; q < 4; q++) acc[i][j][q] = 0.f;

    auto load_chunk = [&](int c, int stage) {
        const size_t coff = (size_t)c * 128;
        const uint32_t aT = sA + stage * ABYTES;
        const uint32_t bT = sB + stage * BBYTES;
#pragma unroll
        for (int i = 0; i < BM / 32; i++) {
            int seg = tid + i * 256, row = seg >> 3, so = (seg & 7) * 16;
            CP_ASYNC16(aT + SMEM_SWZ(row * 128 + so), Ag + (size_t)row * rowB + coff + so);
        }
#pragma unroll
        for (int i = 0; i < BN / 32; i++) {
            int seg = tid + i * 256, row = seg >> 3, so = (seg & 7) * 16;
            CP_ASYNC16(bT + SMEM_SWZ(row * 128 + so), Bg + (size_t)row * rowB + coff + so);
        }
    };

    load_chunk(0, 0); CP_COMMIT();
    load_chunk(1, 1); CP_COMMIT();

    const int a_row = wm * TM + (lane & 15);
    const int a_k16 = (lane >> 4) * 16;
    const int b_row = wn * TN + (lane & 7) + ((lane >> 4) << 3);
    const int b_k16 = ((lane >> 3) & 1) * 16;

    for (int c = 0; c < NC; c++) {
        int n = c + 2;
        if (n < NC) load_chunk(n, n % S_ST);
        CP_COMMIT();
        CP_WAIT2();
        __syncthreads();

        const uint32_t aT = sA + (c % S_ST) * ABYTES;
        const uint32_t bT = sB + (c % S_ST) * BBYTES;
#pragma unroll
        for (int ks = 0; ks < 4; ks++) {
            uint32_t af[MT][4], bfr[NT][2];
#pragma unroll
            for (int i = 0; i < MT; i++)
                ldmx4(af[i], aT + SMEM_SWZ((a_row + i * 16) * 128 + ks * 32 + a_k16));
#pragma unroll
            for (int jp = 0; jp < NT / 2; jp++) {
                uint32_t t4[4];
                ldmx4(t4, bT + SMEM_SWZ((b_row + jp * 16) * 128 + ks * 32 + b_k16));
                bfr[2 * jp][0] = t4[0]; bfr[2 * jp][1] = t4[1];
                bfr[2 * jp + 1][0] = t4[2]; bfr[2 * jp + 1][1] = t4[3];
            }
#pragma unroll
            for (int i = 0; i < MT; i++)
#pragma unroll
                for (int j = 0; j < NT; j++)
                    mma16816(acc[i][j], af[i], bfr[j]);
        }
        __syncthreads();
    }

#pragma unroll
    for (int i = 0; i < MT; i++) {
        const int r0 = bm + wm * TM + i * 16 + (lane >> 2);
        const int r1 = r0 + 8;
#pragma unroll
        for (int j = 0; j < NT; j++) {
            const int col = bn + wn * TN + j * 8 + (lane & 3) * 2;
            const float2 bv = *(const float2*)&bias[col];
            float v00 = acc[i][j][0] + bv.x, v01 = acc[i][j][1] + bv.y;
            float v10 = acc[i][j][2] + bv.x, v11 = acc[i][j][3] + bv.y;
            if (OUTMODE == 0) {
                *(float2*)&Cf[(size_t)r0 * Ntot + col] = make_float2(v00, v01);
                *(float2*)&Cf[(size_t)r1 * Ntot + col] = make_float2(v10, v11);
            } else if (OUTMODE == 1) {
                int b0i = r0 >> 7, t0 = r0 & 127, b1i = r1 >> 7, t1 = r1 & 127;
                int c0p = (col & 1023) * 4 + (col >> 10);
                int c1p = ((col + 1) & 1023) * 4 + ((col + 1) >> 10);
                float* q0 = Cf + ((size_t)t0 * B_SZ + b0i) * Ntot;
                float* q1 = Cf + ((size_t)t1 * B_SZ + b1i) * Ntot;
                q0[c0p] = v00; q0[c1p] = v01;
                q1[c0p] = v10; q1[c1p] = v11;
            } else {
                v00 = fmaxf(v00, 0.f); v01 = fmaxf(v01, 0.f);
                v10 = fmaxf(v10, 0.f); v11 = fmaxf(v11, 0.f);
                bf16 h0, l0, h1, l1;
                bf16* row0 = Cb + (size_t)r0 * 3 * Ntot;
                bf16* row1 = Cb + (size_t)r1 * 3 * Ntot;
                split2(v00, h0, l0); split2(v01, h1, l1);
                *(__nv_bfloat162*)&row0[col] = __nv_bfloat162(h0, h1);
                *(__nv_bfloat162*)&row0[Ntot + col] = __nv_bfloat162(h0, h1);
                *(__nv_bfloat162*)&row0[2 * Ntot + col] = __nv_bfloat162(l0, l1);
                split2(v10, h0, l0); split2(v11, h1, l1);
                *(__nv_bfloat162*)&row1[col] = __nv_bfloat162(h0, h1);
                *(__nv_bfloat162*)&row1[Ntot + col] = __nv_bfloat162(h0, h1);
                *(__nv_bfloat162*)&row1[2 * Ntot + col] = __nv_bfloat162(l0, l1);
            }
        }
    }
}

// ---------------- wavefront recurrent GEMM -----------------------------------
// grid 144: CTAs 0..47 -> L0 (16 tiles x 3 K-splits of 1024 over K=3072),
//           CTAs 48..143 -> L1 (16 tiles x 6 K-splits of 1024 over K=6144).
// L0 processes t=s (active s<128); L1 processes t=s-1 (active s>=1).
// A = g_Acat [64][6144]; B per group; output split-K partials (permuted cols).
__global__ __launch_bounds__(256, 1) void wave_gemm(int s)
{
    constexpr int ABY = 8192;      // 64 x 128B
    constexpr int BBY = 32768;     // 256 x 128B
    extern __shared__ __align__(1024) char smem[];
    const uint32_t sA = smem_u32(smem);
    const uint32_t sB = sA + S_ST * ABY;

    const int tid = threadIdx.x;
    const int lane = tid & 31, wid = tid >> 5;
    const bool gA = blockIdx.x < 48;
    if (gA && s >= 128) return;
    if (!gA && s < 1) return;

    int tile, ks;
    const char* Bg; size_t brs; float* zp;
    if (gA) {
        tile = blockIdx.x / 3; ks = blockIdx.x % 3;
        Bg = (const char*)g_Bwh0 + (size_t)tile * 256 * 6144 + (size_t)ks * 2048;
        brs = 6144;
        zp = g_zpA[ks];
    } else {
        int bb = blockIdx.x - 48;
        tile = bb / 6; ks = bb % 6;
        Bg = (const char*)g_Bcat1 + (size_t)tile * 256 * 12288 + (size_t)ks * 2048;
        brs = 12288;
        zp = g_zpB[ks];
    }
    const char* Ag = (const char*)g_Acat + (size_t)ks * 2048;

    const int wm = wid & 1, wn = wid >> 1;   // TM=32, TN=64 -> MT=2, NT=8
    float acc[2][8][4];
#pragma unroll
    for (int i = 0; i < 2; i++)
#pragma unroll
        for (int j = 0; j < 8; j++)
#pragma unroll
            for (int q = 0; q < 4; q++) acc[i][j][q] = 0.f;

    auto load_chunk = [&](int c, int st) {
        const size_t coff = (size_t)c * 128;
        const uint32_t aT = sA + st * ABY;
        const uint32_t bT = sB + st * BBY;
#pragma unroll
        for (int i = 0; i < 2; i++) {            // A: 64 x 8 segs = 512
            int seg = tid + i * 256, row = seg >> 3, so = (seg & 7) * 16;
            CP_ASYNC16(aT + SMEM_SWZ(row * 128 + so), Ag + (size_t)row * 12288 + coff + so);
        }
#pragma unroll
        for (int i = 0; i < 8; i++) {            // B: 256 x 8 segs = 2048
            int seg = tid + i * 256, row = seg >> 3, so = (seg & 7) * 16;
            CP_ASYNC16(bT + SMEM_SWZ(row * 128 + so), Bg + (size_t)row * brs + coff + so);
        }
    };

    load_chunk(0, 0); CP_COMMIT();
    load_chunk(1, 1); CP_COMMIT();

    const int a_row = wm * 32 + (lane & 15);
    const int a_k16 = (lane >> 4) * 16;
    const int b_row = wn * 64 + (lane & 7) + ((lane >> 4) << 3);
    const int b_k16 = ((lane >> 3) & 1) * 16;

    for (int c = 0; c < 16; c++) {
        int n = c + 2;
        if (n < 16) load_chunk(n, n % S_ST);
        CP_COMMIT();
        CP_WAIT2();
        __syncthreads();
        const uint32_t aT = sA + (c % S_ST) * ABY;
        const uint32_t bT = sB + (c % S_ST) * BBY;
#pragma unroll
        for (int k4 = 0; k4 < 4; k4++) {
            uint32_t af[2][4], bfr[8][2];
#pragma unroll
            for (int i = 0; i < 2; i++)
                ldmx4(af[i], aT + SMEM_SWZ((a_row + i * 16) * 128 + k4 * 32 + a_k16));
#pragma unroll
            for (int jp = 0; jp < 4; jp++) {
                uint32_t t4[4];
                ldmx4(t4, bT + SMEM_SWZ((b_row + jp * 16) * 128 + k4 * 32 + b_k16));
                bfr[2 * jp][0] = t4[0]; bfr[2 * jp][1] = t4[1];
                bfr[2 * jp + 1][0] = t4[2]; bfr[2 * jp + 1][1] = t4[3];
            }
#pragma unroll
            for (int i = 0; i < 2; i++)
#pragma unroll
                for (int j = 0; j < 8; j++)
                    mma16816(acc[i][j], af[i], bfr[j]);
        }
        __syncthreads();
    }

#pragma unroll
    for (int i = 0; i < 2; i++) {
        const int r0 = wm * 32 + i * 16 + (lane >> 2);
#pragma unroll
        for (int j = 0; j < 8; j++) {
            const int col = tile * 256 + wn * 64 + j * 8 + (lane & 3) * 2;
            *(float2*)&zp[(size_t)r0 * G_SZ + col] = make_float2(acc[i][j][0], acc[i][j][1]);
            *(float2*)&zp[(size_t)(r0 + 8) * G_SZ + col] = make_float2(acc[i][j][2], acc[i][j][3]);
        }
    }
}

// ---------------- wavefront gates --------------------------------------------
// grid 256: CTAs 0..127 -> L0 gates (t=s), CTAs 128..255 -> L1 gates (t=s-1).
__global__ __launch_bounds__(256) void wave_gates(
    const float* __restrict__ zx, const float* __restrict__ b1,
    bf16* __restrict__ Aseq1, int s)
{
    const int g = blockIdx.x, tid = threadIdx.x;
    if (g < 128) {
        if (s >= 128) return;
        const float* zx_t = zx + (size_t)s * B_SZ * G_SZ;
#pragma unroll
        for (int rep = 0; rep < 2; rep++) {
            int idx = g * 256 + tid + rep * 32768;      // 0..65535
            int b = idx >> 10, u = idx & 1023;
            size_t zo = (size_t)b * G_SZ + u * 4;
            float4 z = *(const float4*)&zx_t[zo];
#pragma unroll
            for (int p = 0; p < 3; p++) {
                float4 pz = *(const float4*)&g_zpA[p][zo];
                z.x += pz.x; z.y += pz.y; z.z += pz.z; z.w += pz.w;
            }
            int ci = b * H_SZ + u;
            float cn = sigmoidf_(z.y) * g_cst[ci] + sigmoidf_(z.x) * tanhf(z.z);
            float hn = sigmoidf_(z.w) * tanhf(cn);
            g_cst[ci] = cn;
            g_hst[ci] = hn;
            bf16 hi, lo; split2(hn, hi, lo);
            bf16* ra = g_Acat + (size_t)b * 6144;
            ra[u] = hi; ra[1024 + u] = hi; ra[2048 + u] = lo;
        }
    } else {
        if (s < 1) return;
        const int t = s - 1;
#pragma unroll
        for (int rep = 0; rep < 2; rep++) {
            int idx = (g - 128) * 256 + tid + rep * 32768;
            int b = idx >> 10, u = idx & 1023;
            size_t zo = (size_t)b * G_SZ + u * 4;
            float4 z = make_float4(b1[u], b1[1024 + u], b1[2048 + u], b1[3072 + u]);
#pragma unroll
            for (int p = 0; p < 6; p++) {
                float4 pz = *(const float4*)&g_zpB[p][zo];
                z.x += pz.x; z.y += pz.y; z.z += pz.z; z.w += pz.w;
            }
            int ci = B_SZ * H_SZ + b * H_SZ + u;
            float cn = sigmoidf_(z.y) * g_cst[ci] + sigmoidf_(z.x) * tanhf(z.z);
            float hn = sigmoidf_(z.w) * tanhf(cn);
            g_cst[ci] = cn;
            g_hst[ci] = hn;
            bf16 hi, lo; split2(hn, hi, lo);
            bf16* ra = g_Acat + (size_t)b * 6144 + 3072;
            ra[u] = hi; ra[1024 + u] = hi; ra[2048 + u] = lo;
            bf16* rq = Aseq1 + ((size_t)b * T_SZ + t) * 3072;
            rq[u] = hi; rq[1024 + u] = hi; rq[2048 + u] = lo;
        }
    }
}

// ---------------- weight convert: W[K,N] -> dest rows [hi|lo|hi] -------------
// dest row n (permuted if PERMN) has row-stride RS elems, K-block offset koff.
template <int PERMN>
__global__ __launch_bounds__(256) void conv_w(const float* __restrict__ W,
    bf16* __restrict__ Bp, int K, int N, int RS, int koff)
{
    __shared__ float tile[32][33];
    const int n0 = blockIdx.x * 32, k0 = blockIdx.y * 32;
    const int tx = threadIdx.x & 31, ty = threadIdx.x >> 5;
    for (int i = ty; i < 32; i += 8)
        tile[i][tx] = W[(size_t)(k0 + i) * N + n0 + tx];
    __syncthreads();
    for (int i = ty; i < 32; i += 8) {
        int n = n0 + i, k = k0 + tx;
        int np = PERMN ? ((n & 1023) * 4 + (n >> 10)) : n;
        bf16 hi, lo; split2(tile[tx][i], hi, lo);
        bf16* row = Bp + (size_t)np * RS + koff;
        row[k] = hi; row[K + k] = lo; row[2 * K + k] = hi;
    }
}

// ---------------- activation convert: X[M,K] -> A'[M,3K] = [hi|hi|lo] -------
__global__ __launch_bounds__(256) void conv_x(const float* __restrict__ X,
                                              bf16* __restrict__ Ap, int K, int total)
{
    int i = blockIdx.x * 256 + threadIdx.x;
    if (i >= total) return;
    int r = i / K, k = i - r * K;
    bf16 hi, lo; split2(X[i], hi, lo);
    bf16* row = Ap + (size_t)r * 3 * K;
    row[k] = hi; row[K + k] = hi; row[2 * K + k] = lo;
}

// ---------------- LayerNorm + ReLU -> split bf16 ----------------------------
__global__ __launch_bounds__(256) void ln_relu(const float* __restrict__ buf,
    const float* __restrict__ gamma, const float* __restrict__ beta,
    bf16* __restrict__ Ap)
{
    __shared__ float rs[8], rs2[8];
    const int row = blockIdx.x;
    const float* p = buf + (size_t)row * P_SZ;
    const int tid = threadIdx.x;
    float4 v = *(const float4*)&p[tid * 4];
    float s = v.x + v.y + v.z + v.w;
    float s2 = v.x * v.x + v.y * v.y + v.z * v.z + v.w * v.w;
#pragma unroll
    for (int off = 16; off > 0; off >>= 1) {
        s += __shfl_xor_sync(0xFFFFFFFFu, s, off);
        s2 += __shfl_xor_sync(0xFFFFFFFFu, s2, off);
    }
    if ((tid & 31) == 0) { rs[tid >> 5] = s; rs2[tid >> 5] = s2; }
    __syncthreads();
    float tot = 0.f, tot2 = 0.f;
#pragma unroll
    for (int i = 0; i < 8; i++) { tot += rs[i]; tot2 += rs2[i]; }
    const float mu = tot * (1.f / 1024.f);
    const float r = rsqrtf(tot2 * (1.f / 1024.f) - mu * mu + 1e-6f);
    float4 g = *(const float4*)&gamma[tid * 4];
    float4 b = *(const float4*)&beta[tid * 4];
    float o[4] = { fmaxf((v.x - mu) * r * g.x + b.x, 0.f),
                   fmaxf((v.y - mu) * r * g.y + b.y, 0.f),
                   fmaxf((v.z - mu) * r * g.z + b.z, 0.f),
                   fmaxf((v.w - mu) * r * g.w + b.w, 0.f) };
    bf16* rp = Ap + (size_t)row * 3 * P_SZ;
#pragma unroll
    for (int q = 0; q < 4; q++) {
        int k = tid * 4 + q;
        bf16 hi, lo; split2(o[q], hi, lo);
        rp[k] = hi; rp[P_SZ + k] = hi; rp[2 * P_SZ + k] = lo;
    }
}

// ---------------- state init / export ---------------------------------------
__global__ __launch_bounds__(256) void init_state(
    const float* __restrict__ c0, const float* __restrict__ h0)
{
    int i = blockIdx.x * 256 + threadIdx.x;      // 0 .. 131071
    int l = i >> 16, r = i & 65535, b = r >> 10, u = r & 1023;
    g_cst[i] = c0[i];
    g_hst[i] = h0[i];
    bf16 hi, lo; split2(h0[i], hi, lo);
    bf16* ra = g_Acat + (size_t)b * 6144 + l * 3072;
    ra[u] = hi; ra[1024 + u] = hi; ra[2048 + u] = lo;
}
__global__ __launch_bounds__(256) void copy_out(float* __restrict__ out)
{
    int i = blockIdx.x * 256 + threadIdx.x;      // 0 .. 131071
    out[i] = g_cst[i];
    out[131072 + i] = g_hst[i];
}

// ---------------- launch -----------------------------------------------------
extern "C" void kernel_launch(void* const* d_in, const int* in_sizes, int n_in,
                              void* d_out, int out_size)
{
    const float* x        = (const float*)d_in[0];
    const float* c0       = (const float*)d_in[1];
    const float* h0       = (const float*)d_in[2];
    const float* W_pre    = (const float*)d_in[3];
    const float* b_pre    = (const float*)d_in[4];
    const float* ln_scale = (const float*)d_in[5];
    const float* ln_bias  = (const float*)d_in[6];
    const float* Wi0      = (const float*)d_in[7];
    const float* Wh0      = (const float*)d_in[8];
    const float* b0       = (const float*)d_in[9];
    const float* Wi1      = (const float*)d_in[10];
    const float* Wh1      = (const float*)d_in[11];
    const float* b1       = (const float*)d_in[12];
    const float* W_post   = (const float*)d_in[13];
    const float* b_post   = (const float*)d_in[14];
    const float* W_out    = (const float*)d_in[15];
    const float* b_out    = (const float*)d_in[16];
    float* out = (float*)d_out;

    float *pre_p, *zx_p;
    bf16 *Ax, *Aln, *As1, *Ahp;
    bf16 *Bpre, *Bwi0, *Bwh0, *Bcat1, *Bpost, *Bout;
    cudaGetSymbolAddress((void**)&pre_p, g_pre);
    cudaGetSymbolAddress((void**)&zx_p, g_zx);
    cudaGetSymbolAddress((void**)&Ax, g_Ax);
    cudaGetSymbolAddress((void**)&Aln, g_Aln);
    cudaGetSymbolAddress((void**)&As1, g_Aseq1);
    cudaGetSymbolAddress((void**)&Ahp, g_Ahp);
    cudaGetSymbolAddress((void**)&Bpre, g_Bpre);
    cudaGetSymbolAddress((void**)&Bwi0, g_Bwi0);
    cudaGetSymbolAddress((void**)&Bwh0, g_Bwh0);
    cudaGetSymbolAddress((void**)&Bcat1, g_Bcat1);
    cudaGetSymbolAddress((void**)&Bpost, g_Bpost);
    cudaGetSymbolAddress((void**)&Bout, g_Bout);

    const int SMEM_128_128 = S_ST * (128 + 128) * 128;   // 98304
    const int SMEM_128_32  = S_ST * (128 + 32) * 128;    // 61440
    const int SMEM_WV      = S_ST * (64 + 256) * 128;    // 122880
    cudaFuncSetAttribute(gemm_mma<128, 128, 0>, cudaFuncAttributeMaxDynamicSharedMemorySize, SMEM_128_128);
    cudaFuncSetAttribute(gemm_mma<128, 128, 1>, cudaFuncAttributeMaxDynamicSharedMemorySize, SMEM_128_128);
    cudaFuncSetAttribute(gemm_mma<128, 128, 2>, cudaFuncAttributeMaxDynamicSharedMemorySize, SMEM_128_128);
    cudaFuncSetAttribute(gemm_mma<128, 32, 0>,  cudaFuncAttributeMaxDynamicSharedMemorySize, SMEM_128_32);
    cudaFuncSetAttribute(wave_gemm,             cudaFuncAttributeMaxDynamicSharedMemorySize, SMEM_WV);

    // weight + input conversion
    conv_w<0><<<dim3(P_SZ / 32, F_SZ / 32), 256>>>(W_pre, Bpre, F_SZ, P_SZ, 3 * F_SZ, 0);
    conv_w<0><<<dim3(G_SZ / 32, P_SZ / 32), 256>>>(Wi0, Bwi0, P_SZ, G_SZ, 3 * P_SZ, 0);
    conv_w<1><<<dim3(G_SZ / 32, H_SZ / 32), 256>>>(Wh0, Bwh0, H_SZ, G_SZ, 3 * H_SZ, 0);
    conv_w<1><<<dim3(G_SZ / 32, H_SZ / 32), 256>>>(Wi1, Bcat1, H_SZ, G_SZ, 6144, 0);
    conv_w<1><<<dim3(G_SZ / 32, H_SZ / 32), 256>>>(Wh1, Bcat1, H_SZ, G_SZ, 6144, 3072);
    conv_w<0><<<dim3(P_SZ / 32, H_SZ / 32), 256>>>(W_post, Bpost, H_SZ, P_SZ, 3 * H_SZ, 0);
    conv_w<0><<<dim3(A_SZ / 32, P_SZ / 32), 256>>>(W_out, Bout, P_SZ, A_SZ, 3 * P_SZ, 0);
    conv_x<<<(R_SZ * F_SZ + 255) / 256, 256>>>(x, Ax, F_SZ, R_SZ * F_SZ);

    // pre dense -> fp32, then LN+relu -> split bf16
    gemm_mma<128, 128, 0><<<dim3(P_SZ / 128, R_SZ / 128), 256, SMEM_128_128>>>(
        Ax, Bpre, b_pre, pre_p, nullptr, P_SZ, 3 * F_SZ);
    ln_relu<<<R_SZ, 256>>>(pre_p, ln_scale, ln_bias, Aln);

    // layer-0 input gates for all timesteps (time-major, permuted cols)
    gemm_mma<128, 128, 1><<<dim3(G_SZ / 128, R_SZ / 128), 256, SMEM_128_128>>>(
        Aln, Bwi0, b0, zx_p, nullptr, G_SZ, 3 * P_SZ);

    // wavefront recurrence: step s runs L0 t=s and L1 t=s-1
    init_state<<<512, 256>>>(c0, h0);
    for (int s = 0; s <= T_SZ; s++) {
        wave_gemm<<<144, 256, SMEM_WV>>>(s);
        wave_gates<<<256, 256>>>(zx_p, b1, As1, s);
    }
    copy_out<<<512, 256>>>(out);

    // post dense + relu -> split bf16, then logits
    gemm_mma<128, 128, 2><<<dim3(P_SZ / 128, R_SZ / 128), 256, SMEM_128_128>>>(
        As1, Bpost, b_post, nullptr, Ahp, P_SZ, 3 * H_SZ);
    gemm_mma<128, 32, 0><<<dim3(1, R_SZ / 128), 256, SMEM_128_32>>>(
        Ahp, Bout, b_out, out + 4 * B_SZ * H_SZ, nullptr, A_SZ, 3 * P_SZ);
}